// round 6
// baseline (speedup 1.0000x reference)
#include <cuda_runtime.h>
#include <cuda_bf16.h>

#define N_NODES 50000
#define N_EDGES 800000
#define HID 64
#define IN_DIM 4
#define BN_EPS 1e-5f

#define SCAN_BLK 256
#define NBLK ((N_NODES + SCAN_BLK - 1) / SCAN_BLK)   // 196
static_assert(NBLK <= 256, "NBLK must fit one scan block");

// ---------------- scratch (static device globals; no allocation) ----------------
// NOTE: these symbols are ONLY referenced inside device code, or passed to
// kernels via cudaGetSymbolAddress (host code must NEVER pass the bare symbol:
// that passes the host shadow address, which GB300's ATS silently dereferences
// into host memory -> zeros).
__device__ __align__(16) int   g_deg[N_NODES];
__device__ __align__(16) float g_dinv[N_NODES];
__device__ __align__(16) int   g_rowptr[N_NODES + 1];
__device__ __align__(16) int   g_cursor[N_NODES];
__device__ __align__(16) int   g_src[N_EDGES];
__device__ __align__(16) float g_w[N_EDGES];
__device__ __align__(16) float g_h[N_NODES * HID];
__device__ __align__(16) float g_hw[N_NODES * HID];
__device__ __align__(16) int   g_blocksum[NBLK];
__device__ __align__(16) int   g_blockoff[NBLK];

// ---------------- graph preprocessing ----------------
__global__ void zero_deg_kernel() {
    int i = blockIdx.x * blockDim.x + threadIdx.x;
    if (i < N_NODES) g_deg[i] = 0;
}

__global__ void count_deg_kernel(const int* __restrict__ edge_index) {
    int e = blockIdx.x * blockDim.x + threadIdx.x;
    if (e < N_EDGES) {
        int dst = edge_index[N_EDGES + e];   // row 1 of [2, E]
        atomicAdd(&g_deg[dst], 1);
    }
}

__global__ void dinv_kernel() {
    int i = blockIdx.x * blockDim.x + threadIdx.x;
    if (i < N_NODES) {
        // reference degree = in-degree over edges + 1 (self loop)
        g_dinv[i] = rsqrtf((float)(g_deg[i] + 1));
    }
}

// ---- scan stage 1: per-block tree reduction of degrees ----
__global__ void scan_reduce_kernel() {
    __shared__ int sdata[SCAN_BLK];
    int b = blockIdx.x, t = threadIdx.x;
    int i = b * SCAN_BLK + t;
    sdata[t] = (i < N_NODES) ? g_deg[i] : 0;
    __syncthreads();
    #pragma unroll
    for (int s = SCAN_BLK / 2; s > 0; s >>= 1) {
        if (t < s) sdata[t] += sdata[t + s];
        __syncthreads();
    }
    if (t == 0) g_blocksum[b] = sdata[0];
}

// ---- scan stage 2: one block scans the 196 block sums (double-buffered) ----
__global__ void scan_offsets_kernel() {
    __shared__ int buf[2][256];
    int t = threadIdx.x;
    buf[0][t] = (t < NBLK) ? g_blocksum[t] : 0;
    int cur = 0;
    __syncthreads();
    #pragma unroll
    for (int off = 1; off < 256; off <<= 1) {
        int x = buf[cur][t];
        if (t >= off) x += buf[cur][t - off];
        buf[1 - cur][t] = x;
        cur = 1 - cur;
        __syncthreads();
    }
    if (t < NBLK) g_blockoff[t] = (t > 0) ? buf[cur][t - 1] : 0;
    if (t == NBLK - 1) g_rowptr[N_NODES] = buf[cur][t];
}

// ---- scan stage 3: per-block scan of degrees + write rowptr/cursor ----
__global__ void scan_write_kernel() {
    __shared__ int buf[2][SCAN_BLK];
    int b = blockIdx.x, t = threadIdx.x;
    int i = b * SCAN_BLK + t;
    int v = (i < N_NODES) ? g_deg[i] : 0;
    buf[0][t] = v;
    int cur = 0;
    __syncthreads();
    #pragma unroll
    for (int off = 1; off < SCAN_BLK; off <<= 1) {
        int x = buf[cur][t];
        if (t >= off) x += buf[cur][t - off];
        buf[1 - cur][t] = x;
        cur = 1 - cur;
        __syncthreads();
    }
    int incl = buf[cur][t];
    int excl = incl - v + g_blockoff[b];
    if (i < N_NODES) {
        g_rowptr[i] = excl;
        g_cursor[i] = excl;
    }
}

__global__ void fill_kernel(const int* __restrict__ edge_index) {
    int e = blockIdx.x * blockDim.x + threadIdx.x;
    if (e < N_EDGES) {
        int src = edge_index[e];              // row 0 of [2, E]
        int dst = edge_index[N_EDGES + e];    // row 1
        int pos = atomicAdd(&g_cursor[dst], 1);
        g_src[pos] = src;
        g_w[pos] = g_dinv[src] * g_dinv[dst];
    }
}

// ---------------- input projection: h = x @ W_in + b_in ----------------
__global__ void in_proj_kernel(const float* __restrict__ x,
                               const float* __restrict__ W_in,
                               const float* __restrict__ b_in) {
    __shared__ float xs[64 * IN_DIM];
    __shared__ float Ws[IN_DIM * HID];
    __shared__ float bs[HID];
    int tid = threadIdx.x;
    int n0 = blockIdx.x * 64;

    if (tid < IN_DIM * HID) Ws[tid] = W_in[tid];
    if (tid < HID) bs[tid] = b_in[tid];
    {
        int node = n0 + (tid >> 2);
        xs[tid] = (node < N_NODES) ? x[n0 * IN_DIM + tid] : 0.f;
    }
    __syncthreads();

    int j = tid & 63;
    int ng = tid >> 6;
    float bj = bs[j];
    float w0 = Ws[0 * HID + j], w1 = Ws[1 * HID + j], w2 = Ws[2 * HID + j], w3 = Ws[3 * HID + j];
    #pragma unroll 4
    for (int nn = 0; nn < 16; nn++) {
        int nloc = ng * 16 + nn;
        int node = n0 + nloc;
        if (node < N_NODES) {
            const float* xr = &xs[nloc * IN_DIM];
            g_h[node * HID + j] = bj + xr[0] * w0 + xr[1] * w1 + xr[2] * w2 + xr[3] * w3;
        }
    }
}

// ---------------- 64x64 GEMM: C = A @ W (+bias, +relu) ----------------
// A and C must be REAL device pointers (resolved via cudaGetSymbolAddress).
__global__ void gemm64_kernel(const float* __restrict__ A,
                              const float* __restrict__ W,
                              const float* __restrict__ bias,
                              int do_relu,
                              float* __restrict__ C) {
    __shared__ float hT[64 * 68];
    __shared__ float Ws[64 * 64];
    int tid = threadIdx.x;
    int n0 = blockIdx.x * 64;

    {
        const float4* W4 = (const float4*)W;
        float4* Ws4 = (float4*)Ws;
        #pragma unroll
        for (int i = tid; i < 1024; i += 256) Ws4[i] = W4[i];
    }
    {
        int nn = tid & 63;
        int kq4 = tid >> 6;
        int node = n0 + nn;
        const float4* A4 = (const float4*)A;
        #pragma unroll
        for (int q = 0; q < 4; q++) {
            int kq = kq4 * 4 + q;
            float4 hv = (node < N_NODES) ? A4[node * 16 + kq]
                                         : make_float4(0.f, 0.f, 0.f, 0.f);
            hT[(kq * 4 + 0) * 68 + nn] = hv.x;
            hT[(kq * 4 + 1) * 68 + nn] = hv.y;
            hT[(kq * 4 + 2) * 68 + nn] = hv.z;
            hT[(kq * 4 + 3) * 68 + nn] = hv.w;
        }
    }
    __syncthreads();

    int nq = tid & 15;
    int jq = tid >> 4;
    const float4* Ws4 = (const float4*)Ws;

    float4 acc0 = make_float4(0.f, 0.f, 0.f, 0.f);
    float4 acc1 = acc0, acc2 = acc0, acc3 = acc0;
    #pragma unroll
    for (int k = 0; k < 64; k++) {
        float4 wv = Ws4[k * 16 + jq];
        float4 hv = *(const float4*)&hT[k * 68 + nq * 4];
        acc0.x += hv.x * wv.x; acc0.y += hv.x * wv.y; acc0.z += hv.x * wv.z; acc0.w += hv.x * wv.w;
        acc1.x += hv.y * wv.x; acc1.y += hv.y * wv.y; acc1.z += hv.y * wv.z; acc1.w += hv.y * wv.w;
        acc2.x += hv.z * wv.x; acc2.y += hv.z * wv.y; acc2.z += hv.z * wv.z; acc2.w += hv.z * wv.w;
        acc3.x += hv.w * wv.x; acc3.y += hv.w * wv.y; acc3.z += hv.w * wv.z; acc3.w += hv.w * wv.w;
    }

    float4 bv = make_float4(0.f, 0.f, 0.f, 0.f);
    if (bias) bv = ((const float4*)bias)[jq];
    float4* C4 = (float4*)C;
    float4 accs[4] = {acc0, acc1, acc2, acc3};
    #pragma unroll
    for (int ni = 0; ni < 4; ni++) {
        int node = n0 + nq * 4 + ni;
        if (node < N_NODES) {
            float4 r = accs[ni];
            r.x += bv.x; r.y += bv.y; r.z += bv.z; r.w += bv.w;
            if (do_relu) {
                r.x = fmaxf(r.x, 0.f); r.y = fmaxf(r.y, 0.f);
                r.z = fmaxf(r.z, 0.f); r.w = fmaxf(r.w, 0.f);
            }
            C4[node * 16 + jq] = r;
        }
    }
}

// ---------------- aggregate + BN + ReLU + residual (warp per node) ----------------
__global__ void agg_kernel(const float* __restrict__ conv_b,
                           const float* __restrict__ bn_gamma,
                           const float* __restrict__ bn_beta,
                           const float* __restrict__ bn_mean,
                           const float* __restrict__ bn_var) {
    int warp = (blockIdx.x * blockDim.x + threadIdx.x) >> 5;
    int lane = threadIdx.x & 31;
    if (warp >= N_NODES) return;
    int v = warp;

    const float2* hw2 = (const float2*)g_hw;
    float2* h2 = (float2*)g_h;

    float dv = g_dinv[v];
    float wself = dv * dv;
    float2 sv = hw2[v * 32 + lane];
    float accx = sv.x * wself;
    float accy = sv.y * wself;

    int beg = g_rowptr[v];
    int end = g_rowptr[v + 1];
    for (int e = beg; e < end; e += 32) {
        int idx = e + lane;
        int mysrc = 0;
        float myw = 0.f;
        if (idx < end) {
            mysrc = g_src[idx];
            myw = g_w[idx];
        }
        int cnt = min(32, end - e);
        for (int j = 0; j < cnt; j++) {
            int s = __shfl_sync(0xffffffffu, mysrc, j);
            float w = __shfl_sync(0xffffffffu, myw, j);
            float2 hv = hw2[s * 32 + lane];
            accx += hv.x * w;
            accy += hv.y * w;
        }
    }

    float2 cb = ((const float2*)conv_b)[lane];
    float2 gm = ((const float2*)bn_gamma)[lane];
    float2 bt = ((const float2*)bn_beta)[lane];
    float2 mn = ((const float2*)bn_mean)[lane];
    float2 vr = ((const float2*)bn_var)[lane];
    float s0 = gm.x * rsqrtf(vr.x + BN_EPS);
    float s1 = gm.y * rsqrtf(vr.y + BN_EPS);
    float o0 = (accx + cb.x - mn.x) * s0 + bt.x;
    float o1 = (accy + cb.y - mn.y) * s1 + bt.y;
    o0 = fmaxf(o0, 0.f);
    o1 = fmaxf(o1, 0.f);
    float2 res = h2[v * 32 + lane];
    h2[v * 32 + lane] = make_float2(o0 + res.x, o1 + res.y);
}

// ---------------- output: out = x + (t @ W2 + b2), t = relu(h@W1+b1) in g_hw ----------------
__global__ void out_final_kernel(const float* __restrict__ x,
                                 const float* __restrict__ W2,
                                 const float* __restrict__ b2,
                                 float* __restrict__ out) {
    __shared__ float ts[64 * 68];
    __shared__ float W2s[HID * IN_DIM];
    __shared__ float b2s[IN_DIM];
    int tid = threadIdx.x;
    int n0 = blockIdx.x * 64;

    if (tid < HID * IN_DIM) W2s[tid] = W2[tid];
    if (tid < IN_DIM) b2s[tid] = b2[tid];
    #pragma unroll
    for (int r = 0; r < 16; r++) {
        int i = tid + 256 * r;
        int nloc = i >> 6;
        int l = i & 63;
        int node = n0 + nloc;
        ts[nloc * 68 + l] = (node < N_NODES) ? g_hw[node * HID + l] : 0.f;
    }
    __syncthreads();

    int nloc = tid >> 2;
    int m = tid & 3;
    int node = n0 + nloc;
    float acc = 0.f;
    #pragma unroll
    for (int l = 0; l < 64; l++) {
        acc += ts[nloc * 68 + l] * W2s[l * IN_DIM + m];
    }
    if (node < N_NODES) {
        out[node * IN_DIM + m] = x[node * IN_DIM + m] + b2s[m] + acc;
    }
}

// ---------------- launch ----------------
extern "C" void kernel_launch(void* const* d_in, const int* in_sizes, int n_in,
                              void* d_out, int out_size) {
    const float* x          = (const float*)d_in[0];
    const int*   edge_index = (const int*)d_in[1];
    const float* W_in       = (const float*)d_in[2];
    const float* b_in       = (const float*)d_in[3];
    const float* conv_w     = (const float*)d_in[4];   // [3,64,64]
    const float* conv_b     = (const float*)d_in[5];   // [3,64]
    const float* bn_gamma   = (const float*)d_in[6];
    const float* bn_beta    = (const float*)d_in[7];
    const float* bn_mean    = (const float*)d_in[8];
    const float* bn_var     = (const float*)d_in[9];
    const float* W1         = (const float*)d_in[10];
    const float* b1         = (const float*)d_in[11];
    const float* W2         = (const float*)d_in[12];
    const float* b2         = (const float*)d_in[13];
    float* out = (float*)d_out;

    // Resolve REAL device addresses of the __device__ globals that get passed
    // as kernel arguments. Passing the bare symbol from host code passes the
    // host shadow address (silently readable via ATS on GB300 -> zeros).
    void* p_h = nullptr;
    void* p_hw = nullptr;
    cudaGetSymbolAddress(&p_h, g_h);
    cudaGetSymbolAddress(&p_hw, g_hw);
    float* d_h = (float*)p_h;
    float* d_hw = (float*)p_hw;

    const int TPB = 256;
    const int gridN = (N_NODES + TPB - 1) / TPB;
    const int gridE = (N_EDGES + TPB - 1) / TPB;
    const int gridT = (N_NODES + 63) / 64;
    const int gridW = (N_NODES * 32 + TPB - 1) / TPB;   // warp per node

    // build graph structure
    zero_deg_kernel<<<gridN, TPB>>>();
    count_deg_kernel<<<gridE, TPB>>>(edge_index);
    dinv_kernel<<<gridN, TPB>>>();
    scan_reduce_kernel<<<NBLK, SCAN_BLK>>>();
    scan_offsets_kernel<<<1, 256>>>();
    scan_write_kernel<<<NBLK, SCAN_BLK>>>();
    fill_kernel<<<gridE, TPB>>>(edge_index);

    // input projection
    in_proj_kernel<<<gridT, TPB>>>(x, W_in, b_in);

    // 3 GCN layers
    for (int i = 0; i < 3; i++) {
        gemm64_kernel<<<gridT, TPB>>>(d_h, conv_w + i * HID * HID, nullptr, 0, d_hw);
        agg_kernel<<<gridW, TPB>>>(conv_b + i * HID,
                                   bn_gamma + i * HID, bn_beta + i * HID,
                                   bn_mean + i * HID, bn_var + i * HID);
    }

    // output MLP: t = relu(h @ W1 + b1) into g_hw, then 64->4 + residual
    gemm64_kernel<<<gridT, TPB>>>(d_h, W1, b1, 1, d_hw);
    out_final_kernel<<<gridT, TPB>>>(x, W2, b2, out);
}